// round 13
// baseline (speedup 1.0000x reference)
#include <cuda_runtime.h>
#include <cuda_fp16.h>

// Problem constants (fixed by the dataset)
#define NN 50000
#define LL 4
#define EE 1600000
#define CC 128
#define NM 8          // m<4 -> phi_inverse[l], m>=4 -> phi[l-4]
#define CAP 72        // fixed row-bin capacity (Poisson(32): P(>72) ~ 5e-10/row)
#define MAXSPILL 4096

#define GEMM_R 16

// ----------------------------------------------------------------------------
// Scratch (static device globals; allocation-free per harness rules)
// ----------------------------------------------------------------------------
__device__ int   g_cnt[NM][NN];                              // row counts / cursors
__device__ __align__(16) int2 g_edge[(size_t)NM * NN * CAP]; // row bins: {col, val bits}
__device__ int   g_nspill;
__device__ int4  g_spill[MAXSPILL];                          // {m, r, c, val bits}
__device__ __align__(16) __half g_Y1[(size_t)LL * NN * CC];  // feats @ W (fp16)
__device__ __align__(16) __half g_Y2[(size_t)LL * NN * CC];  // theta*(phi_inv@Y1) (fp16)

// packed dual fp32 FMA: d.lo += a.lo*b.lo ; d.hi += a.hi*b.hi
__device__ __forceinline__ void ffma2(unsigned long long& d,
                                      unsigned long long a,
                                      unsigned long long b) {
    asm("fma.rn.f32x2 %0, %1, %2, %0;" : "+l"(d) : "l"(a), "l"(b));
}

// ----------------------------------------------------------------------------
// 1) zero counters + spill count
// ----------------------------------------------------------------------------
__global__ void zero_cnt_kernel() {
    int i = blockIdx.x * blockDim.x + threadIdx.x;
    if (i < NM * NN) ((int*)g_cnt)[i] = 0;
    if (i == 0) g_nspill = 0;
}

// ----------------------------------------------------------------------------
// 2) scatter edges directly into fixed-capacity row bins
//    4 edges/thread via int4/float4; grid (EE/512, NM), 128 threads
// ----------------------------------------------------------------------------
__global__ void __launch_bounds__(128) scatter_kernel(
    const int* __restrict__ phi_idx, const float* __restrict__ phi_val,
    const int* __restrict__ inv_idx, const float* __restrict__ inv_val) {
    int m = blockIdx.y;
    const int*   base = (m < LL) ? (inv_idx + (size_t)m * 2 * EE)
                                 : (phi_idx + (size_t)(m - LL) * 2 * EE);
    const float* vals = (m < LL) ? (inv_val + (size_t)m * EE)
                                 : (phi_val + (size_t)(m - LL) * EE);
    int e = blockIdx.x * 512 + threadIdx.x * 4;
    int4   r4 = *(const int4*)(base + e);
    int4   c4 = *(const int4*)(base + EE + e);
    float4 v4 = *(const float4*)(vals + e);

    int rr[4] = {r4.x, r4.y, r4.z, r4.w};
    int cc[4] = {c4.x, c4.y, c4.z, c4.w};
    float vv[4] = {v4.x, v4.y, v4.z, v4.w};
    #pragma unroll
    for (int j = 0; j < 4; j++) {
        int pos = atomicAdd(&g_cnt[m][rr[j]], 1);
        if (pos < CAP) {
            g_edge[((size_t)m * NN + rr[j]) * CAP + pos] =
                make_int2(cc[j], __float_as_int(vv[j]));
        } else {
            int s = atomicAdd(&g_nspill, 1);
            if (s < MAXSPILL)
                g_spill[s] = make_int4(m, rr[j], cc[j], __float_as_int(vv[j]));
        }
    }
}

// ----------------------------------------------------------------------------
// 3) GEMM: Y1 = feats @ W (fp16 out), FFMA2 mainloop, 16 rows/block
// ----------------------------------------------------------------------------
__global__ void __launch_bounds__(128) gemm_kernel(const float* __restrict__ feats,
                                                   const float* __restrict__ W) {
    __shared__ __align__(16) float Ws[CC * 66];      // W half, transposed [c][k], pad 66
    __shared__ __align__(16) float Fs[GEMM_R * CC];  // feature tile [rr][k]
    int tid = threadIdx.x;           // output column c
    int row0 = blockIdx.x * GEMM_R;  // t = l*NN + n

    #pragma unroll
    for (int rr = 0; rr < GEMM_R; rr++) {
        int t = row0 + rr;
        int l = t / NN;
        int n = t - l * NN;
        Fs[rr * CC + tid] = feats[((size_t)n * LL + l) * CC + tid];
    }

    unsigned long long acc[GEMM_R];
    #pragma unroll
    for (int rr = 0; rr < GEMM_R; rr++) acc[rr] = 0ull;

    for (int h = 0; h < 2; h++) {
        __syncthreads();
        #pragma unroll
        for (int i = tid; i < 64 * CC; i += 128) {
            int k = i >> 7;
            int c = i & 127;
            Ws[c * 66 + k] = W[(size_t)(h * 64 + k) * CC + c];
        }
        __syncthreads();

        #pragma unroll
        for (int k = 0; k < 64; k += 4) {
            unsigned long long w01 = *(const unsigned long long*)&Ws[tid * 66 + k];
            unsigned long long w23 = *(const unsigned long long*)&Ws[tid * 66 + k + 2];
            #pragma unroll
            for (int rr = 0; rr < GEMM_R; rr++) {
                ulonglong2 f = *(const ulonglong2*)&Fs[rr * CC + h * 64 + k];
                ffma2(acc[rr], f.x, w01);
                ffma2(acc[rr], f.y, w23);
            }
        }
    }

    #pragma unroll
    for (int rr = 0; rr < GEMM_R; rr++) {
        float lo, hi;
        asm("mov.b64 {%0,%1}, %2;" : "=f"(lo), "=f"(hi) : "l"(acc[rr]));
        float s = lo + hi;
        int t = row0 + rr;
        int l = t / NN;
        int n = t - l * NN;
        g_Y1[(size_t)l * NN * CC + (size_t)n * CC + tid] = __float2half_rn(s);
    }
}

// ----------------------------------------------------------------------------
// 4) SpMM stage 1, per scale: Y2[l] = theta .* (phi_inv[l] @ Y1[l])
//    warp/row; independent broadcast int2 loads, unroll 8
// ----------------------------------------------------------------------------
__global__ void __launch_bounds__(256) spmm_inv_kernel(const float* __restrict__ theta,
                                                       int l) {
    int r = (blockIdx.x * blockDim.x + threadIdx.x) >> 5;   // row in [0, NN)
    unsigned lane = threadIdx.x & 31;
    int cnt = min(__ldg(&g_cnt[l][r]), CAP);
    const uint2* Xv = (const uint2*)(g_Y1 + (size_t)l * NN * CC);
    const int2*  bin = g_edge + ((size_t)l * NN + r) * CAP;

    float4 acc = make_float4(0.f, 0.f, 0.f, 0.f);
    #pragma unroll 8
    for (int e = 0; e < cnt; e++) {
        int2 rec = __ldg(&bin[e]);                // uniform across warp -> broadcast
        float val = __int_as_float(rec.y);
        uint2 xw = Xv[((unsigned)rec.x << 5) | lane];   // 32-bit index math
        float2 fa = __half22float2(*(const half2*)&xw.x);
        float2 fb = __half22float2(*(const half2*)&xw.y);
        acc.x = fmaf(val, fa.x, acc.x);
        acc.y = fmaf(val, fa.y, acc.y);
        acc.z = fmaf(val, fb.x, acc.z);
        acc.w = fmaf(val, fb.y, acc.w);
    }
    float t = __ldg(&theta[r]);
    half2 h0 = __floats2half2_rn(acc.x * t, acc.y * t);
    half2 h1 = __floats2half2_rn(acc.z * t, acc.w * t);
    uint2 o;
    o.x = *(const unsigned int*)&h0;
    o.y = *(const unsigned int*)&h1;
    ((uint2*)(g_Y2 + (size_t)l * NN * CC))[((unsigned)r << 5) | lane] = o;
}

// ----------------------------------------------------------------------------
// 4b) per-scale spill fix-up for stage 1 (normally 0 iterations)
// ----------------------------------------------------------------------------
__global__ void spill_fix1_kernel(const float* __restrict__ theta, int lsel) {
    int n = min(g_nspill, MAXSPILL);
    int tid = threadIdx.x;
    for (int i = 0; i < n; i++) {
        int4 s = g_spill[i];
        if (s.x != lsel) continue;                // this scale's phi_inverse only
        int l = s.x, r = s.y, c = s.z;
        float v = __int_as_float(s.w) * theta[r];
        if (tid < 64) {
            const half2* y1 = (const half2*)(g_Y1 + (size_t)l * NN * CC);
            half2* y2 = (half2*)(g_Y2 + (size_t)l * NN * CC);
            float2 x = __half22float2(y1[(size_t)c * 64 + tid]);
            atomicAdd(&y2[(size_t)r * 64 + tid], __floats2half2_rn(v * x.x, v * x.y));
        }
    }
}

// ----------------------------------------------------------------------------
// 5) SpMM stage 2, per scale: out[n][l][:] = phi[l] @ Y2[l]   (fp32 output)
// ----------------------------------------------------------------------------
__global__ void __launch_bounds__(256) spmm_phi_kernel(float* __restrict__ outp,
                                                       int l) {
    int r = (blockIdx.x * blockDim.x + threadIdx.x) >> 5;
    unsigned lane = threadIdx.x & 31;
    int m = LL + l;
    int cnt = min(__ldg(&g_cnt[m][r]), CAP);
    const uint2* Xv = (const uint2*)(g_Y2 + (size_t)l * NN * CC);
    const int2*  bin = g_edge + ((size_t)m * NN + r) * CAP;

    float4 acc = make_float4(0.f, 0.f, 0.f, 0.f);
    #pragma unroll 8
    for (int e = 0; e < cnt; e++) {
        int2 rec = __ldg(&bin[e]);                // uniform across warp -> broadcast
        float val = __int_as_float(rec.y);
        uint2 xw = Xv[((unsigned)rec.x << 5) | lane];
        float2 fa = __half22float2(*(const half2*)&xw.x);
        float2 fb = __half22float2(*(const half2*)&xw.y);
        acc.x = fmaf(val, fa.x, acc.x);
        acc.y = fmaf(val, fa.y, acc.y);
        acc.z = fmaf(val, fb.x, acc.z);
        acc.w = fmaf(val, fb.y, acc.w);
    }
    ((float4*)outp)[((unsigned)(r * LL + l) << 5) | lane] = acc;   // [n][l][c]
}

// ----------------------------------------------------------------------------
// 5b) global spill fix-up for stage 2 (after all phi; normally 0 iterations)
// ----------------------------------------------------------------------------
__global__ void spill_fix2_kernel(float* __restrict__ outp) {
    int n = min(g_nspill, MAXSPILL);
    int tid = threadIdx.x;
    for (int i = 0; i < n; i++) {
        int4 s = g_spill[i];
        if (s.x < LL) continue;                   // stage-2 handles m>=4 only
        int l = s.x - LL, r = s.y, c = s.z;
        float v = __int_as_float(s.w);
        const half2* y2 = (const half2*)(g_Y2 + (size_t)l * NN * CC);
        float2 x = __half22float2(y2[(size_t)c * 64 + (tid >> 1)]);
        float xv = (tid & 1) ? x.y : x.x;
        atomicAdd(&outp[((size_t)r * LL + l) * CC + tid], v * xv);
    }
}

// ----------------------------------------------------------------------------
// launch: fork-join front + per-scale software pipeline for the SpMM chain
//   s1: zero -> scatter -[evS]
//   c : gemm --- wait(evS) -> inv(0)[eI0] -> inv(1)[eI1] -> inv(2)[eI2] -> inv(3)[eI3]
//   s2: wait eI(l) -> spill1(l) -> phi(l)   (l = 0..3, pipelined vs inv(l+1))
//   c : wait evP -> spill2
// ----------------------------------------------------------------------------
extern "C" void kernel_launch(void* const* d_in, const int* in_sizes, int n_in,
                              void* d_out, int out_size) {
    const int*   phi_idx = (const int*)d_in[0];    // [L,2,E]
    const float* phi_val = (const float*)d_in[1];  // [L,E]
    const int*   inv_idx = (const int*)d_in[2];    // [L,2,E]
    const float* inv_val = (const float*)d_in[3];  // [L,E]
    const float* feats   = (const float*)d_in[4];  // [N,L,C]
    const float* W       = (const float*)d_in[5];  // [C,C]
    const float* theta   = (const float*)d_in[6];  // [N]
    float*       outp    = (float*)d_out;          // [N,L,C]

    static cudaStream_t s1 = nullptr, s2 = nullptr;
    static cudaEvent_t evRoot = nullptr, evS = nullptr, evP = nullptr;
    static cudaEvent_t eI[LL] = {nullptr, nullptr, nullptr, nullptr};
    if (s1 == nullptr) {
        cudaStreamCreateWithFlags(&s1, cudaStreamNonBlocking);
        cudaStreamCreateWithFlags(&s2, cudaStreamNonBlocking);
        cudaEventCreateWithFlags(&evRoot, cudaEventDisableTiming);
        cudaEventCreateWithFlags(&evS,    cudaEventDisableTiming);
        cudaEventCreateWithFlags(&evP,    cudaEventDisableTiming);
        for (int l = 0; l < LL; l++)
            cudaEventCreateWithFlags(&eI[l], cudaEventDisableTiming);
    }

    // fork
    cudaEventRecord(evRoot, 0);
    cudaStreamWaitEvent(s1, evRoot, 0);

    // bin build on s1 (latency-bound; SM pipes mostly idle)
    zero_cnt_kernel<<<(NM * NN + 255) / 256, 256, 0, s1>>>();
    dim3 gE(EE / 512, NM);
    scatter_kernel<<<gE, 128, 0, s1>>>(phi_idx, phi_val, inv_idx, inv_val);
    cudaEventRecord(evS, s1);

    // GEMM on capture stream, concurrent with scatter
    gemm_kernel<<<(LL * NN) / GEMM_R, 128>>>(feats, W);

    // join, then pipelined SpMM: inv chain on capture stream
    cudaStreamWaitEvent(0, evS, 0);
    for (int l = 0; l < LL; l++) {
        spmm_inv_kernel<<<NN / 8, 256>>>(theta, l);
        cudaEventRecord(eI[l], 0);
    }

    // phi chain on s2, each scale gated on its inv
    for (int l = 0; l < LL; l++) {
        cudaStreamWaitEvent(s2, eI[l], 0);
        spill_fix1_kernel<<<1, 128, 0, s2>>>(theta, l);
        spmm_phi_kernel<<<NN / 8, 256, 0, s2>>>(outp, l);
    }
    cudaEventRecord(evP, s2);

    // rejoin capture stream; stage-2 spill fix-up last
    cudaStreamWaitEvent(0, evP, 0);
    spill_fix2_kernel<<<1, 128>>>(outp);
}

// round 16
// speedup vs baseline: 1.1671x; 1.1671x over previous
#include <cuda_runtime.h>
#include <cuda_fp16.h>

// Problem constants (fixed by the dataset)
#define NN 50000
#define LL 4
#define EE 1600000
#define CC 128
#define NM 8          // m<4 -> phi_inverse[l], m>=4 -> phi[l-4]
#define CAP 72        // fixed row-bin capacity (Poisson(32): P(>72) ~ 5e-10/row)
#define MAXSPILL 4096

#define GEMM_R 16
#define SC_BLK 1024                     // edges per scatter block (8/thread * 128)
#define SC_GRID ((EE + SC_BLK - 1) / SC_BLK)   // 1563 (last block partial: 512 edges)

// ----------------------------------------------------------------------------
// Scratch (static device globals; allocation-free per harness rules)
// ----------------------------------------------------------------------------
__device__ int   g_cnt[NM][NN];                              // row counts / cursors
__device__ __align__(16) int2 g_edge[(size_t)NM * NN * CAP]; // row bins: {col, val bits}
__device__ int   g_nspill;
__device__ int4  g_spill[MAXSPILL];                          // {m, r, c, val bits}
__device__ __align__(16) __half g_Y1[(size_t)LL * NN * CC];  // feats @ W (fp16)
__device__ __align__(16) __half g_Y2[(size_t)LL * NN * CC];  // theta*(phi_inv@Y1) (fp16)

// packed dual fp32 FMA: d.lo += a.lo*b.lo ; d.hi += a.hi*b.hi
__device__ __forceinline__ void ffma2(unsigned long long& d,
                                      unsigned long long a,
                                      unsigned long long b) {
    asm("fma.rn.f32x2 %0, %1, %2, %0;" : "+l"(d) : "l"(a), "l"(b));
}

// ----------------------------------------------------------------------------
// 1) zero counters + spill count
// ----------------------------------------------------------------------------
__global__ void zero_cnt_kernel() {
    int i = blockIdx.x * blockDim.x + threadIdx.x;
    if (i < NM * NN) ((int*)g_cnt)[i] = 0;
    if (i == 0) g_nspill = 0;
}

// ----------------------------------------------------------------------------
// 2) scatter edges into fixed-capacity row bins
//    8 edges/thread; ALL atomics issued first (8-deep MLP), then all stores.
//    grid (SC_GRID, NM), 128 threads; guarded tail for the partial last block
// ----------------------------------------------------------------------------
__global__ void __launch_bounds__(128) scatter_kernel(
    const int* __restrict__ phi_idx, const float* __restrict__ phi_val,
    const int* __restrict__ inv_idx, const float* __restrict__ inv_val) {
    int m = blockIdx.y;
    const int*   base = (m < LL) ? (inv_idx + (size_t)m * 2 * EE)
                                 : (phi_idx + (size_t)(m - LL) * 2 * EE);
    const float* vals = (m < LL) ? (inv_val + (size_t)m * EE)
                                 : (phi_val + (size_t)(m - LL) * EE);
    int e = blockIdx.x * SC_BLK + threadIdx.x * 8;
    int2* eg = g_edge + (size_t)m * NN * CAP;

    if (e + 8 <= EE) {
        // fast path: full 8-edge group
        int4   ra = *(const int4*)(base + e);
        int4   rb = *(const int4*)(base + e + 4);
        int4   ca = *(const int4*)(base + EE + e);
        int4   cb = *(const int4*)(base + EE + e + 4);
        float4 va = *(const float4*)(vals + e);
        float4 vb = *(const float4*)(vals + e + 4);

        int rr[8] = {ra.x, ra.y, ra.z, ra.w, rb.x, rb.y, rb.z, rb.w};
        int cc[8] = {ca.x, ca.y, ca.z, ca.w, cb.x, cb.y, cb.z, cb.w};
        float vv[8] = {va.x, va.y, va.z, va.w, vb.x, vb.y, vb.z, vb.w};

        // phase 1: 8 independent atomics (front-batched -> 8-deep MLP)
        int pos[8];
        #pragma unroll
        for (int j = 0; j < 8; j++)
            pos[j] = atomicAdd(&g_cnt[m][rr[j]], 1);

        // phase 2: stores (each depends only on its own atomic result)
        #pragma unroll
        for (int j = 0; j < 8; j++) {
            if (pos[j] < CAP) {
                eg[(size_t)rr[j] * CAP + pos[j]] =
                    make_int2(cc[j], __float_as_int(vv[j]));
            } else {
                int s = atomicAdd(&g_nspill, 1);
                if (s < MAXSPILL)
                    g_spill[s] = make_int4(m, rr[j], cc[j], __float_as_int(vv[j]));
            }
        }
    } else {
        // guarded tail (last partial block only)
        for (int j = 0; j < 8; j++) {
            int ej = e + j;
            if (ej >= EE) break;
            int   r = base[ej];
            int   c = base[EE + ej];
            float v = vals[ej];
            int pos = atomicAdd(&g_cnt[m][r], 1);
            if (pos < CAP) {
                eg[(size_t)r * CAP + pos] = make_int2(c, __float_as_int(v));
            } else {
                int s = atomicAdd(&g_nspill, 1);
                if (s < MAXSPILL)
                    g_spill[s] = make_int4(m, r, c, __float_as_int(v));
            }
        }
    }
}

// ----------------------------------------------------------------------------
// 3) GEMM: Y1 = feats @ W (fp16 out), FFMA2 mainloop, 16 rows/block
// ----------------------------------------------------------------------------
__global__ void __launch_bounds__(128) gemm_kernel(const float* __restrict__ feats,
                                                   const float* __restrict__ W) {
    __shared__ __align__(16) float Ws[CC * 66];      // W half, transposed [c][k], pad 66
    __shared__ __align__(16) float Fs[GEMM_R * CC];  // feature tile [rr][k]
    int tid = threadIdx.x;           // output column c
    int row0 = blockIdx.x * GEMM_R;  // t = l*NN + n

    #pragma unroll
    for (int rr = 0; rr < GEMM_R; rr++) {
        int t = row0 + rr;
        int l = t / NN;
        int n = t - l * NN;
        Fs[rr * CC + tid] = feats[((size_t)n * LL + l) * CC + tid];
    }

    unsigned long long acc[GEMM_R];
    #pragma unroll
    for (int rr = 0; rr < GEMM_R; rr++) acc[rr] = 0ull;

    for (int h = 0; h < 2; h++) {
        __syncthreads();
        #pragma unroll
        for (int i = tid; i < 64 * CC; i += 128) {
            int k = i >> 7;
            int c = i & 127;
            Ws[c * 66 + k] = W[(size_t)(h * 64 + k) * CC + c];
        }
        __syncthreads();

        #pragma unroll
        for (int k = 0; k < 64; k += 4) {
            unsigned long long w01 = *(const unsigned long long*)&Ws[tid * 66 + k];
            unsigned long long w23 = *(const unsigned long long*)&Ws[tid * 66 + k + 2];
            #pragma unroll
            for (int rr = 0; rr < GEMM_R; rr++) {
                ulonglong2 f = *(const ulonglong2*)&Fs[rr * CC + h * 64 + k];
                ffma2(acc[rr], f.x, w01);
                ffma2(acc[rr], f.y, w23);
            }
        }
    }

    #pragma unroll
    for (int rr = 0; rr < GEMM_R; rr++) {
        float lo, hi;
        asm("mov.b64 {%0,%1}, %2;" : "=f"(lo), "=f"(hi) : "l"(acc[rr]));
        float s = lo + hi;
        int t = row0 + rr;
        int l = t / NN;
        int n = t - l * NN;
        g_Y1[(size_t)l * NN * CC + (size_t)n * CC + tid] = __float2half_rn(s);
    }
}

// ----------------------------------------------------------------------------
// 4) SpMM stage 1: Y2[l] = theta .* (phi_inv[l] @ Y1[l])
//    warp/row; independent broadcast int2 loads, unroll 4 (proven R10 form)
// ----------------------------------------------------------------------------
__global__ void __launch_bounds__(256) spmm_inv_kernel(const float* __restrict__ theta) {
    int wg   = (blockIdx.x * blockDim.x + threadIdx.x) >> 5;
    unsigned lane = threadIdx.x & 31;
    int l = wg / NN;
    int r = wg - l * NN;
    int cnt = min(__ldg(&g_cnt[l][r]), CAP);
    const uint2* Xv = (const uint2*)(g_Y1 + (size_t)l * NN * CC);
    const int2*  bin = g_edge + ((size_t)l * NN + r) * CAP;

    float4 acc = make_float4(0.f, 0.f, 0.f, 0.f);
    #pragma unroll 4
    for (int e = 0; e < cnt; e++) {
        int2 rec = __ldg(&bin[e]);                // uniform across warp -> broadcast
        float val = __int_as_float(rec.y);
        uint2 xw = Xv[((unsigned)rec.x << 5) | lane];   // 32-bit index math
        float2 fa = __half22float2(*(const half2*)&xw.x);
        float2 fb = __half22float2(*(const half2*)&xw.y);
        acc.x = fmaf(val, fa.x, acc.x);
        acc.y = fmaf(val, fa.y, acc.y);
        acc.z = fmaf(val, fb.x, acc.z);
        acc.w = fmaf(val, fb.y, acc.w);
    }
    float t = __ldg(&theta[r]);
    half2 h0 = __floats2half2_rn(acc.x * t, acc.y * t);
    half2 h1 = __floats2half2_rn(acc.z * t, acc.w * t);
    uint2 o;
    o.x = *(const unsigned int*)&h0;
    o.y = *(const unsigned int*)&h1;
    ((uint2*)(g_Y2 + (size_t)l * NN * CC))[((unsigned)r << 5) | lane] = o;
}

// ----------------------------------------------------------------------------
// 4b) spill fix-up for stage 1 (normally 0 iterations)
// ----------------------------------------------------------------------------
__global__ void spill_fix1_kernel(const float* __restrict__ theta) {
    int n = min(g_nspill, MAXSPILL);
    int tid = threadIdx.x;
    for (int i = 0; i < n; i++) {
        int4 s = g_spill[i];
        if (s.x >= LL) continue;                  // stage-1 handles m<4 only
        int l = s.x, r = s.y, c = s.z;
        float v = __int_as_float(s.w) * theta[r];
        if (tid < 64) {
            const half2* y1 = (const half2*)(g_Y1 + (size_t)l * NN * CC);
            half2* y2 = (half2*)(g_Y2 + (size_t)l * NN * CC);
            float2 x = __half22float2(y1[(size_t)c * 64 + tid]);
            atomicAdd(&y2[(size_t)r * 64 + tid], __floats2half2_rn(v * x.x, v * x.y));
        }
    }
}

// ----------------------------------------------------------------------------
// 5) SpMM stage 2: out[n][l][:] = phi[l] @ Y2[l]   (fp32 output, R10 form)
// ----------------------------------------------------------------------------
__global__ void __launch_bounds__(256) spmm_phi_kernel(float* __restrict__ outp) {
    int wg   = (blockIdx.x * blockDim.x + threadIdx.x) >> 5;
    unsigned lane = threadIdx.x & 31;
    int l = wg / NN;
    int r = wg - l * NN;
    int m = LL + l;
    int cnt = min(__ldg(&g_cnt[m][r]), CAP);
    const uint2* Xv = (const uint2*)(g_Y2 + (size_t)l * NN * CC);
    const int2*  bin = g_edge + ((size_t)m * NN + r) * CAP;

    float4 acc = make_float4(0.f, 0.f, 0.f, 0.f);
    #pragma unroll 4
    for (int e = 0; e < cnt; e++) {
        int2 rec = __ldg(&bin[e]);                // uniform across warp -> broadcast
        float val = __int_as_float(rec.y);
        uint2 xw = Xv[((unsigned)rec.x << 5) | lane];   // 32-bit index math
        float2 fa = __half22float2(*(const half2*)&xw.x);
        float2 fb = __half22float2(*(const half2*)&xw.y);
        acc.x = fmaf(val, fa.x, acc.x);
        acc.y = fmaf(val, fa.y, acc.y);
        acc.z = fmaf(val, fb.x, acc.z);
        acc.w = fmaf(val, fb.y, acc.w);
    }
    ((float4*)outp)[((unsigned)(r * LL + l) << 5) | lane] = acc;   // [n][l][c]
}

// ----------------------------------------------------------------------------
// 5b) spill fix-up for stage 2 (normally 0 iterations)
// ----------------------------------------------------------------------------
__global__ void spill_fix2_kernel(float* __restrict__ outp) {
    int n = min(g_nspill, MAXSPILL);
    int tid = threadIdx.x;
    for (int i = 0; i < n; i++) {
        int4 s = g_spill[i];
        if (s.x < LL) continue;                   // stage-2 handles m>=4 only
        int l = s.x - LL, r = s.y, c = s.z;
        float v = __int_as_float(s.w);
        const half2* y2 = (const half2*)(g_Y2 + (size_t)l * NN * CC);
        float2 x = __half22float2(y2[(size_t)c * 64 + (tid >> 1)]);
        float xv = (tid & 1) ? x.y : x.x;
        atomicAdd(&outp[((size_t)r * LL + l) * CC + tid], v * xv);
    }
}

// ----------------------------------------------------------------------------
// launch: minimal fork-join (R10 structure, the 724.6us baseline)
//   s1: zero -> scatter -[evS]
//   s0: gemm --- wait(evS) -> spmm_inv -> spill1 -> spmm_phi -> spill2
// ----------------------------------------------------------------------------
extern "C" void kernel_launch(void* const* d_in, const int* in_sizes, int n_in,
                              void* d_out, int out_size) {
    const int*   phi_idx = (const int*)d_in[0];    // [L,2,E]
    const float* phi_val = (const float*)d_in[1];  // [L,E]
    const int*   inv_idx = (const int*)d_in[2];    // [L,2,E]
    const float* inv_val = (const float*)d_in[3];  // [L,E]
    const float* feats   = (const float*)d_in[4];  // [N,L,C]
    const float* W       = (const float*)d_in[5];  // [C,C]
    const float* theta   = (const float*)d_in[6];  // [N]
    float*       outp    = (float*)d_out;          // [N,L,C]

    static cudaStream_t s1 = nullptr;
    static cudaEvent_t evRoot = nullptr, evS = nullptr;
    if (s1 == nullptr) {
        cudaStreamCreateWithFlags(&s1, cudaStreamNonBlocking);
        cudaEventCreateWithFlags(&evRoot, cudaEventDisableTiming);
        cudaEventCreateWithFlags(&evS,    cudaEventDisableTiming);
    }

    // fork
    cudaEventRecord(evRoot, 0);
    cudaStreamWaitEvent(s1, evRoot, 0);

    // bin build on s1 (latency-bound; SM pipes mostly idle)
    zero_cnt_kernel<<<(NM * NN + 255) / 256, 256, 0, s1>>>();
    dim3 gE(SC_GRID, NM);
    scatter_kernel<<<gE, 128, 0, s1>>>(phi_idx, phi_val, inv_idx, inv_val);
    cudaEventRecord(evS, s1);

    // GEMM on capture stream, concurrent with scatter
    gemm_kernel<<<(LL * NN) / GEMM_R, 128>>>(feats, W);

    // join, then SpMM chain
    cudaStreamWaitEvent(0, evS, 0);
    spmm_inv_kernel<<<(LL * NN) / 8, 256>>>(theta);
    spill_fix1_kernel<<<1, 128>>>(theta);
    spmm_phi_kernel<<<(LL * NN) / 8, 256>>>(outp);
    spill_fix2_kernel<<<1, 128>>>(outp);
}